// round 13
// baseline (speedup 1.0000x reference)
#include <cuda_runtime.h>
#include <cstdint>

#define B_MAX   8
#define P_MAX   140000
#define NBINS   4096
#define CAP     8192       // compact buffer per batch (power of two)
#define NMS_K   5000       // candidates considered by NMS
#define NWORDS  157        // ceil(5000/32)
#define PAD     5120       // padded row length (i-dim) of transposed matrix
#define TOPK    750        // rows emitted per class
#define CONF_TH 0.05f
#define NMS_TH  0.3f
#define FULL    0xffffffffu
#define LOGIT05 -2.9444389791664403f   // logit(0.05)
#define PH1_W   64                      // phase-1 word range [0,64)
#define PH1_I   (PH1_W * 32)            // = 2048 candidates
#define ITILE0  64                      // phase-0 i-tile (shorter critical path)
#define ITILE1  128                     // phase-1 i-tile
#define SGRID   24                      // score grid x-dim

// ---------------- scratch (static device globals; no allocation) ----------------
__device__ unsigned int       g_hist  [B_MAX * NBINS];
__device__ int                g_done  [B_MAX];
__device__ int                g_cnt   [B_MAX];
__device__ int                g_cutbin[B_MAX];
__device__ unsigned long long g_keys  [B_MAX * CAP];
__device__ unsigned long long g_keys2 [B_MAX * CAP];
__device__ float              g_cscore[B_MAX * NMS_K];
__device__ float4             g_cbox  [B_MAX * NMS_K];
__device__ float              g_carea [B_MAX * NMS_K];
__device__ unsigned int       g_matT  [(size_t)B_MAX * NWORDS * PAD];   // ~25.6 MB
// sweep state handoff
__device__ int                g_acc   [B_MAX * TOPK];
__device__ int                g_scnt  [B_MAX];
__device__ int                g_sdone [B_MAX];
__device__ int                g_need;

__device__ __forceinline__ int d_bin(float d) {
    int bin = (int)fmaf(d, 256.0f, 768.0f);        // monotone in d
    return bin > NBINS - 1 ? NBINS - 1 : (bin < 0 ? 0 : bin);
}

// keep predicate: fast d-test with exact softmax fallback in the boundary band
__device__ __forceinline__ bool keep_pred(float c0, float c1, float d) {
    if (fabsf(d - LOGIT05) < 1e-3f) {
        float m  = fmaxf(c0, c1);
        float e0 = expf(c0 - m);
        float e1 = expf(c1 - m);
        return __fdiv_rn(e1, e0 + e1) > CONF_TH;
    }
    return d > LOGIT05;
}

// ---------------- fused: zero out + histogram + (last block) cutoff + scratch reset ----------------
__global__ void score_cut_kernel(const float* __restrict__ conf, float* __restrict__ out,
                                 int out_size, int P) {
    __shared__ unsigned hist[NBINS];
    __shared__ int s_last;
    int b = blockIdx.y;
    int tid = threadIdx.x;

    // zero output (spread over all blocks)
    {
        int t = (blockIdx.y * gridDim.x + blockIdx.x) * blockDim.x + tid;
        int stride = gridDim.x * gridDim.y * blockDim.x;
        for (int i = t; i < out_size; i += stride) out[i] = 0.0f;
    }

    for (int i = tid; i < NBINS; i += blockDim.x) hist[i] = 0u;
    __syncthreads();
    int stride = gridDim.x * blockDim.x;
    const float2* cp = reinterpret_cast<const float2*>(conf) + (size_t)b * P;
    for (int i = blockIdx.x * blockDim.x + tid; i < P; i += stride) {
        float2 c = cp[i];
        float d = c.y - c.x;                         // sigmoid(d) == softmax class-1
        if (keep_pred(c.x, c.y, d))
            atomicAdd(&hist[d_bin(d)], 1u);
    }
    __syncthreads();
    for (int i = tid; i < NBINS; i += blockDim.x)
        if (hist[i]) atomicAdd(&g_hist[b * NBINS + i], hist[i]);

    // last block per batch computes the cutoff and resets scratch
    __threadfence();
    if (tid == 0) {
        int old = atomicAdd(&g_done[b], 1);
        s_last = (old == (int)gridDim.x - 1);
    }
    __syncthreads();
    if (!s_last) return;

    __shared__ unsigned csum[256];
    unsigned sum = 0;
    #pragma unroll
    for (int i = 0; i < NBINS / 256; i++) sum += g_hist[b * NBINS + tid * (NBINS / 256) + i];
    csum[tid] = sum;
    __syncthreads();
    if (tid == 0) {
        unsigned acc = 0;
        int c = 255;
        for (; c >= 0; c--) {
            if (acc + csum[c] >= (unsigned)NMS_K) break;
            acc += csum[c];
        }
        int cut = 0;
        if (c >= 0) {
            int bin = c * (NBINS / 256) + (NBINS / 256) - 1;
            for (; bin >= c * (NBINS / 256); bin--) {
                acc += g_hist[b * NBINS + bin];
                if (acc >= (unsigned)NMS_K) break;
            }
            cut = (bin < c * (NBINS / 256)) ? c * (NBINS / 256) : bin;
        }
        g_cutbin[b] = cut;
        g_cnt[b]  = 0;      // reset for compact (this run)
        g_need    = 0;      // reset for sweep1 (this run)
        g_done[b] = 0;      // reset for next run
    }
    __syncthreads();
    // zero hist for next run (read is complete)
    for (int i = tid; i < NBINS; i += blockDim.x) g_hist[b * NBINS + i] = 0u;
}

// ---------------- compact: recompute d, keep bin>=cut-1, exact s, sortable keys ----------------
__global__ void compact_kernel(const float* __restrict__ conf, int P) {
    int b = blockIdx.y;
    int lane = threadIdx.x & 31;
    int base = (blockIdx.x * blockDim.x + threadIdx.x) * 4;   // 4 anchors/thread
    int cut  = g_cutbin[b] - 1; if (cut < 0) cut = 0;         // one-bin margin (d vs s rounding)
    unsigned long long keys[4];
    int c = 0;
    if (base < P) {
        const float4* cp4 = reinterpret_cast<const float4*>(conf + (size_t)b * P * 2);
        float4 ca = cp4[base / 2];
        float4 cb = cp4[base / 2 + 1];
        float c0s[4] = {ca.x, ca.z, cb.x, cb.z};
        float c1s[4] = {ca.y, ca.w, cb.y, cb.w};
        #pragma unroll
        for (int q = 0; q < 4; q++) {
            if (base + q < P) {
                float c0 = c0s[q], c1 = c1s[q];
                float d = c1 - c0;
                if (keep_pred(c0, c1, d) && d_bin(d) >= cut) {
                    float m  = fmaxf(c0, c1);
                    float e0 = expf(c0 - m);
                    float e1 = expf(c1 - m);
                    float s  = __fdiv_rn(e1, e0 + e1);       // exact ref recipe
                    unsigned kb = __float_as_uint(s);
                    keys[c++] = ((unsigned long long)(~kb) << 32) | (unsigned)(base + q);
                }
            }
        }
    }
    unsigned cnt = (unsigned)c;
    #pragma unroll
    for (int dd = 1; dd < 32; dd <<= 1) {
        unsigned n = __shfl_up_sync(FULL, cnt, dd);
        if (lane >= dd) cnt += n;
    }
    unsigned tot = __shfl_sync(FULL, cnt, 31);
    int basepos = 0;
    if (lane == 31 && tot) basepos = atomicAdd(&g_cnt[b], (int)tot);
    basepos = __shfl_sync(FULL, basepos, 31);
    int pos = basepos + (int)(cnt - (unsigned)c);
    for (int q = 0; q < c; q++, pos++)
        if (pos < CAP) g_keys[(size_t)b * CAP + pos] = keys[q];
}

// ---------------- stage A: bitonic sort each 2048-chunk ascending (local direction) ----------------
__global__ void sort2048_kernel() {
    __shared__ unsigned long long sm[2048];
    int b = blockIdx.y, chunk = blockIdx.x, tid = threadIdx.x, T = blockDim.x;
    int gbase = chunk * 2048;
    int cnt = g_cnt[b]; if (cnt > CAP) cnt = CAP;
    for (int i = tid; i < 2048; i += T)
        sm[i] = (gbase + i < cnt) ? g_keys[(size_t)b * CAP + gbase + i] : ~0ull;
    __syncthreads();
    for (int k = 2; k <= 2048; k <<= 1) {
        for (int j = k >> 1; j > 0; j >>= 1) {
            for (int i = tid; i < 2048; i += T) {
                int ixj = i ^ j;
                if (ixj > i) {
                    unsigned long long a = sm[i], cc = sm[ixj];
                    bool up = ((i & k) == 0);           // LOCAL direction: chunk fully ascending
                    if ((a > cc) == up) { sm[i] = cc; sm[ixj] = a; }
                }
            }
            __syncthreads();
        }
    }
    for (int i = tid; i < 2048; i += T) g_keys[(size_t)b * CAP + gbase + i] = sm[i];
}

// ---------------- merge-path merge of two sorted seg-length lists (smem-staged) ----------------
// dir=0: g_keys -> g_keys2.  dir=1: g_keys2 -> g_keys (+ decode top NMS_K when final).
__global__ void merge_kernel(int seg, int dir, int final,
                             const float* __restrict__ loc, const float* __restrict__ prior,
                             int P) {
    extern __shared__ unsigned long long sm[];   // [2*seg]
    int b = blockIdx.y, pairid = blockIdx.x, tid = threadIdx.x, T = blockDim.x;
    const unsigned long long* src = dir ? g_keys2 : g_keys;
    unsigned long long*       dst = dir ? g_keys  : g_keys2;
    size_t base = (size_t)b * CAP + (size_t)pairid * 2 * seg;
    int n2 = 2 * seg;
    for (int i = tid; i < n2; i += T) sm[i] = src[base + i];
    __syncthreads();
    const unsigned long long* A  = sm;
    const unsigned long long* Bv = sm + seg;
    int Q = n2 / T;                  // outputs per thread
    int d = tid * Q;
    // merge-path binary search: ia = #elements taken from A before diagonal d
    int lo = d - seg; if (lo < 0) lo = 0;
    int hi = d < seg ? d : seg;
    while (lo < hi) {
        int mid = (lo + hi) >> 1;
        if (A[mid] < Bv[d - 1 - mid]) lo = mid + 1; else hi = mid;
    }
    int ia = lo, ib = d - lo;
    for (int q = 0; q < Q; q++) {
        bool fromA = (ib >= seg) || (ia < seg && A[ia] < Bv[ib]);
        unsigned long long key = fromA ? A[ia++] : Bv[ib++];
        int outpos = d + q;
        if (!final) {
            dst[base + outpos] = key;
        } else if (outpos < NMS_K) {
            unsigned idx = (unsigned)key;
            int o = b * NMS_K + outpos;
            if (idx < (unsigned)P) {
                float  sc = __uint_as_float(~(unsigned)(key >> 32));
                float4 l  = reinterpret_cast<const float4*>(loc)[(size_t)b * P + idx];
                float4 pr = reinterpret_cast<const float4*>(prior)[idx];
                float cx = pr.x + l.x * 0.1f * pr.z;
                float cy = pr.y + l.y * 0.1f * pr.w;
                float w  = pr.z * expf(l.z * 0.2f);
                float h  = pr.w * expf(l.w * 0.2f);
                float x1 = cx - w * 0.5f;
                float y1 = cy - h * 0.5f;
                float x2 = x1 + w;
                float y2 = y1 + h;
                g_cscore[o] = sc;
                g_cbox[o]   = make_float4(x1, y1, x2, y2);
                g_carea[o]  = (x2 - x1) * (y2 - y1);
            } else {
                g_cscore[o] = -1.0f;
                g_cbox[o]   = make_float4(0.f, 0.f, 0.f, 0.f);
                g_carea[o]  = 0.0f;
            }
        }
    }
}

// ---------------- suppression bitmatrix (transposed), phased ----------------
__global__ __launch_bounds__(256) void matrix_kernel(int phase, int itile) {
    if (phase && g_need == 0) return;
    __shared__ float4 sbi[ITILE1];
    __shared__ float  sai[ITILE1];
    int b  = blockIdx.y;
    int i0 = blockIdx.x * itile;
    int tid = threadIdx.x, lane = tid & 31, wid = tid >> 5;   // 8 warps

    for (int q = tid; q < itile; q += 256) {
        int i = i0 + q;
        if (i < NMS_K) { sbi[q] = g_cbox[b * NMS_K + i]; sai[q] = g_carea[b * NMS_K + i]; }
        else           { sbi[q] = make_float4(0,0,0,0);  sai[q] = 0.f; }
    }
    __syncthreads();

    int ilim = min(itile, NMS_K - i0);
    int wstart = i0 >> 5;
    int wend   = NWORDS;
    if (phase == 0) wend = PH1_W;
    else if (i0 < PH1_I) wstart = PH1_W;

    for (int w = wstart + wid; w < wend; w += 8) {
        int j = w * 32 + lane;
        bool jv = j < NMS_K;
        float4 bj = jv ? g_cbox[b * NMS_K + j] : make_float4(0,0,0,0);
        float  aj = jv ? g_carea[b * NMS_K + j] : 0.f;
        size_t base = ((size_t)(b * NWORDS + w)) * PAD + i0;
        unsigned myw = 0;
        for (int ii = 0; ii < ilim; ii++) {
            int i = i0 + ii;
            float4 bi = sbi[ii];                      // broadcast (conflict-free)
            float  ai = sai[ii];
            float xx1 = fmaxf(bj.x, bi.x), yy1 = fmaxf(bj.y, bi.y);
            float xx2 = fminf(bj.z, bi.z), yy2 = fminf(bj.w, bi.w);
            float inter = fmaxf(xx2 - xx1, 0.f) * fmaxf(yy2 - yy1, 0.f);
            float uni   = aj - inter + ai;
            // division-free IoU sign test; exact __fdiv_rn only in the boundary band
            float d = fmaf(-NMS_TH, uni, inter);
            bool flag;
            if (fabsf(d) <= 1e-6f * fabsf(uni))
                flag = __fdiv_rn(inter, uni) > NMS_TH;
            else
                flag = d > 0.f;
            flag = flag && jv && (j > i);
            unsigned bal = __ballot_sync(FULL, flag);
            if ((ii & 31) == lane) myw = bal;
            if ((ii & 31) == 31) g_matT[base + (ii - 31) + lane] = myw;   // coalesced
        }
        if (ilim & 31) g_matT[base + (ilim & ~31) + lane] = myw;
    }
}

// ---------------- sweep phase 1: 4-word groups (latency batching); emits if done ----------------
__global__ void sweep1_kernel(float* __restrict__ out) {
    __shared__ unsigned validw[PH1_W];
    __shared__ int      s_acc[TOPK];
    __shared__ int      s_cnt;

    int b = blockIdx.x, tid = threadIdx.x, lane = tid & 31, wid = tid >> 5;

    for (int w = wid; w < PH1_W; w += 8) {
        int i = w * 32 + lane;
        unsigned m = __ballot_sync(FULL, (i < NMS_K) && (g_cscore[b * NMS_K + i] > 0.0f));
        if (lane == 0) validw[w] = m;
    }
    __syncthreads();

    if (wid == 0) {
        int cnt = 0;
        for (int wg = 0; wg < PH1_W && cnt < TOPK; wg += 4) {
            int I0 = wg * 32;
            size_t rowb[4];
            unsigned rem[4], pre[4][4];
            #pragma unroll
            for (int k = 0; k < 4; k++) {
                rowb[k] = ((size_t)(b * NWORDS + wg + k)) * PAD;
                unsigned r = 0;
                for (int q = lane; q < cnt; q += 32) r |= g_matT[rowb[k] + s_acc[q]];
                rem[k] = r;
                #pragma unroll
                for (int a = 0; a <= k; a++)
                    pre[k][a] = g_matT[rowb[k] + I0 + a * 32 + lane];
            }
            #pragma unroll
            for (int k = 0; k < 4; k++) rem[k] = __reduce_or_sync(FULL, rem[k]);
            #pragma unroll
            for (int a = 0; a < 4; a++) {
                if (cnt >= TOPK) break;
                unsigned avail = validw[wg + a] & ~rem[a];
                while (avail && cnt < TOPK) {
                    int bit = __ffs(avail) - 1;
                    if (lane == 0) s_acc[cnt] = I0 + a * 32 + bit;
                    cnt++;
                    avail &= ~(1u << bit);
                    avail &= ~__shfl_sync(FULL, pre[a][a], bit);
                    #pragma unroll
                    for (int k2 = 0; k2 < 4; k2++)
                        if (k2 > a) rem[k2] |= __shfl_sync(FULL, pre[k2][a], bit);
                }
            }
            __syncwarp();
        }
        if (lane == 0) {
            s_cnt = cnt;
            g_scnt[b] = cnt;
            int done = (cnt >= TOPK);
            g_sdone[b] = done;
            if (!done) atomicOr(&g_need, 1);
        }
    }
    __syncthreads();

    int cnt = s_cnt;
    if (cnt >= TOPK) {
        float* orow = out + ((size_t)b * 2 + 1) * TOPK * 5;
        for (int t = tid; t < cnt; t += blockDim.x) {
            int i = s_acc[t];
            float4 bb = g_cbox[b * NMS_K + i];
            float  sc = g_cscore[b * NMS_K + i];
            float* r = orow + t * 5;
            r[0] = sc; r[1] = bb.x; r[2] = bb.y; r[3] = bb.z; r[4] = bb.w;
        }
    } else {
        for (int t = tid; t < cnt; t += blockDim.x) g_acc[b * TOPK + t] = s_acc[t];
    }
}

// ---------------- sweep phase 2: resume + emit (only for unfinished batches) ----------------
__global__ void sweep2_kernel(float* __restrict__ out) {
    __shared__ unsigned validw[NWORDS];
    __shared__ int      s_acc[TOPK];
    __shared__ int      s_cnt;

    int b = blockIdx.x, tid = threadIdx.x, lane = tid & 31, wid = tid >> 5;
    if (g_sdone[b]) return;                       // emitted in sweep1
    int cnt0 = g_scnt[b];

    for (int t = tid; t < cnt0; t += blockDim.x) s_acc[t] = g_acc[b * TOPK + t];
    if (tid == 0) s_cnt = cnt0;

    for (int w = PH1_W + wid; w < NWORDS; w += 8) {
        int i = w * 32 + lane;
        unsigned m = __ballot_sync(FULL, (i < NMS_K) && (g_cscore[b * NMS_K + i] > 0.0f));
        if (lane == 0) validw[w] = m;
    }
    __syncthreads();

    if (wid == 0) {
        int cnt = cnt0;
        for (int w = PH1_W; w < NWORDS && cnt < TOPK; w++) {
            size_t base = ((size_t)(b * NWORDS + w)) * PAD;
            unsigned rem = 0;
            for (int q = lane; q < cnt; q += 32)
                rem |= g_matT[base + s_acc[q]];
            rem = __reduce_or_sync(FULL, rem);
            unsigned pre = g_matT[base + w * 32 + lane];
            unsigned avail = validw[w] & ~rem;
            while (avail && cnt < TOPK) {
                int bit = __ffs(avail) - 1;
                int i = w * 32 + bit;
                if (lane == 0) s_acc[cnt] = i;
                cnt++;
                avail &= ~(1u << bit);
                avail &= ~__shfl_sync(FULL, pre, bit);
            }
            __syncwarp();
        }
        if (lane == 0) s_cnt = cnt;
    }
    __syncthreads();

    int cnt = s_cnt;
    float* orow = out + ((size_t)b * 2 + 1) * TOPK * 5;   // class 1
    for (int t = tid; t < cnt; t += blockDim.x) {
        int i = s_acc[t];
        float4 bb = g_cbox[b * NMS_K + i];
        float  sc = g_cscore[b * NMS_K + i];
        float* r = orow + t * 5;
        r[0] = sc; r[1] = bb.x; r[2] = bb.y; r[3] = bb.z; r[4] = bb.w;
    }
}

// ---------------- launch ----------------
extern "C" void kernel_launch(void* const* d_in, const int* in_sizes, int n_in,
                              void* d_out, int out_size) {
    const float* loc   = (const float*)d_in[0];   // [B,P,4]
    const float* conf  = (const float*)d_in[1];   // [B,P,2]
    const float* prior = (const float*)d_in[2];   // [P,4]

    int P = in_sizes[2] / 4;
    int B = in_sizes[1] / (2 * P);
    if (B > B_MAX) B = B_MAX;
    if (P > P_MAX) P = P_MAX;

    float* out = (float*)d_out;

    cudaFuncSetAttribute(merge_kernel, cudaFuncAttributeMaxDynamicSharedMemorySize, 65536);

    // 1: zero out + histogram + cutoff (last block) + scratch reset
    score_cut_kernel<<<dim3(SGRID, B), 256>>>(conf, out, out_size, P);

    // 2: compact
    dim3 gcomp((P + 1023) / 1024, B);
    compact_kernel<<<gcomp, 256>>>(conf, P);

    // 3: sort four 2048-chunks ascending
    sort2048_kernel<<<dim3(4, B), 1024>>>();

    // 4: merge 2048+2048 -> 4096 (x2), g_keys -> g_keys2
    merge_kernel<<<dim3(2, B), 256, 2 * 2048 * 8>>>(2048, 0, 0, loc, prior, P);

    // 5: merge 4096+4096 -> 8192, g_keys2 -> (decode top NMS_K inline)
    merge_kernel<<<dim3(1, B), 256, 2 * 4096 * 8>>>(4096, 1, 1, loc, prior, P);

    // 6-7: phase-1 matrix (tile 64, short critical path) + grouped sweep
    matrix_kernel<<<dim3(PH1_I / ITILE0, B), 256>>>(0, ITILE0);
    sweep1_kernel<<<B, 256>>>(out);

    // 8-9: phase-2 remainder (early-exits when all batches finished) + resume/emit
    matrix_kernel<<<dim3((NMS_K + ITILE1 - 1) / ITILE1, B), 256>>>(1, ITILE1);
    sweep2_kernel<<<B, 256>>>(out);
}

// round 14
// speedup vs baseline: 1.1438x; 1.1438x over previous
#include <cuda_runtime.h>
#include <cstdint>

#define B_MAX   8
#define P_MAX   140000
#define NBINS   4096
#define CAP     8192       // compact buffer per batch (power of two)
#define NMS_K   5000       // candidates considered by NMS
#define NWORDS  157        // ceil(5000/32)
#define PAD     5120       // padded row length (i-dim) of transposed matrix
#define TOPK    750        // rows emitted per class
#define CONF_TH 0.05f
#define NMS_TH  0.3f
#define FULL    0xffffffffu
#define LOGIT05 -2.9444389791664403f   // logit(0.05)
#define PH1_W   64                      // phase-1 word range [0,64)
#define PH1_I   (PH1_W * 32)            // = 2048 candidates
#define ITILE0  64                      // phase-0 i-tile (shorter critical path)
#define ITILE1  128                     // phase-1 i-tile
#define SGRID   48                      // score grid x-dim (fills the chip for the 8.7MB read)

// ---------------- scratch (static device globals; no allocation) ----------------
__device__ unsigned int       g_hist  [B_MAX * NBINS];
__device__ int                g_done  [B_MAX];
__device__ int                g_cnt   [B_MAX];
__device__ int                g_cutbin[B_MAX];
__device__ unsigned long long g_keys  [B_MAX * CAP];
__device__ unsigned long long g_keys2 [B_MAX * CAP];
__device__ float              g_cscore[B_MAX * NMS_K];
__device__ float4             g_cbox  [B_MAX * NMS_K];
__device__ float              g_carea [B_MAX * NMS_K];
__device__ unsigned int       g_matT  [(size_t)B_MAX * NWORDS * PAD];   // ~25.6 MB
// sweep state handoff
__device__ int                g_acc   [B_MAX * TOPK];
__device__ int                g_scnt  [B_MAX];
__device__ int                g_sdone [B_MAX];
__device__ int                g_need;

__device__ __forceinline__ int d_bin(float d) {
    int bin = (int)fmaf(d, 256.0f, 768.0f);        // monotone in d
    return bin > NBINS - 1 ? NBINS - 1 : (bin < 0 ? 0 : bin);
}

// keep predicate: fast d-test with exact softmax fallback in the boundary band
__device__ __forceinline__ bool keep_pred(float c0, float c1, float d) {
    if (fabsf(d - LOGIT05) < 1e-3f) {
        float m  = fmaxf(c0, c1);
        float e0 = expf(c0 - m);
        float e1 = expf(c1 - m);
        return __fdiv_rn(e1, e0 + e1) > CONF_TH;
    }
    return d > LOGIT05;
}

// ---------------- fused: zero out + histogram + (last block) cutoff + scratch reset ----------------
__global__ void score_cut_kernel(const float* __restrict__ conf, float* __restrict__ out,
                                 int out_size, int P) {
    __shared__ unsigned hist[NBINS];
    __shared__ int s_last;
    int b = blockIdx.y;
    int tid = threadIdx.x;

    // zero output (spread over all blocks)
    {
        int t = (blockIdx.y * gridDim.x + blockIdx.x) * blockDim.x + tid;
        int stride = gridDim.x * gridDim.y * blockDim.x;
        for (int i = t; i < out_size; i += stride) out[i] = 0.0f;
    }

    for (int i = tid; i < NBINS; i += blockDim.x) hist[i] = 0u;
    __syncthreads();
    int stride = gridDim.x * blockDim.x;
    const float2* cp = reinterpret_cast<const float2*>(conf) + (size_t)b * P;
    for (int i = blockIdx.x * blockDim.x + tid; i < P; i += stride) {
        float2 c = cp[i];
        float d = c.y - c.x;                         // sigmoid(d) == softmax class-1
        if (keep_pred(c.x, c.y, d))
            atomicAdd(&hist[d_bin(d)], 1u);
    }
    __syncthreads();
    for (int i = tid; i < NBINS; i += blockDim.x)
        if (hist[i]) atomicAdd(&g_hist[b * NBINS + i], hist[i]);

    // last block per batch computes the cutoff and resets scratch
    __threadfence();
    if (tid == 0) {
        int old = atomicAdd(&g_done[b], 1);
        s_last = (old == (int)gridDim.x - 1);
    }
    __syncthreads();
    if (!s_last) return;

    __shared__ unsigned csum[256];
    unsigned sum = 0;
    #pragma unroll
    for (int i = 0; i < NBINS / 256; i++) sum += g_hist[b * NBINS + tid * (NBINS / 256) + i];
    csum[tid] = sum;
    __syncthreads();
    if (tid == 0) {
        unsigned acc = 0;
        int c = 255;
        for (; c >= 0; c--) {
            if (acc + csum[c] >= (unsigned)NMS_K) break;
            acc += csum[c];
        }
        int cut = 0;
        if (c >= 0) {
            int bin = c * (NBINS / 256) + (NBINS / 256) - 1;
            for (; bin >= c * (NBINS / 256); bin--) {
                acc += g_hist[b * NBINS + bin];
                if (acc >= (unsigned)NMS_K) break;
            }
            cut = (bin < c * (NBINS / 256)) ? c * (NBINS / 256) : bin;
        }
        g_cutbin[b] = cut;
        g_cnt[b]  = 0;      // reset for compact (this run)
        g_need    = 0;      // reset for sweep1 (this run)
        g_done[b] = 0;      // reset for next run
    }
    __syncthreads();
    // zero hist for next run (read is complete)
    for (int i = tid; i < NBINS; i += blockDim.x) g_hist[b * NBINS + i] = 0u;
}

// ---------------- compact: recompute d, keep bin>=cut-1, exact s, sortable keys ----------------
__global__ void compact_kernel(const float* __restrict__ conf, int P) {
    int b = blockIdx.y;
    int lane = threadIdx.x & 31;
    int base = (blockIdx.x * blockDim.x + threadIdx.x) * 4;   // 4 anchors/thread
    int cut  = g_cutbin[b] - 1; if (cut < 0) cut = 0;         // one-bin margin (d vs s rounding)
    unsigned long long keys[4];
    int c = 0;
    if (base < P) {
        const float4* cp4 = reinterpret_cast<const float4*>(conf + (size_t)b * P * 2);
        float4 ca = cp4[base / 2];
        float4 cb = cp4[base / 2 + 1];
        float c0s[4] = {ca.x, ca.z, cb.x, cb.z};
        float c1s[4] = {ca.y, ca.w, cb.y, cb.w};
        #pragma unroll
        for (int q = 0; q < 4; q++) {
            if (base + q < P) {
                float c0 = c0s[q], c1 = c1s[q];
                float d = c1 - c0;
                if (keep_pred(c0, c1, d) && d_bin(d) >= cut) {
                    float m  = fmaxf(c0, c1);
                    float e0 = expf(c0 - m);
                    float e1 = expf(c1 - m);
                    float s  = __fdiv_rn(e1, e0 + e1);       // exact ref recipe
                    unsigned kb = __float_as_uint(s);
                    keys[c++] = ((unsigned long long)(~kb) << 32) | (unsigned)(base + q);
                }
            }
        }
    }
    unsigned cnt = (unsigned)c;
    #pragma unroll
    for (int dd = 1; dd < 32; dd <<= 1) {
        unsigned n = __shfl_up_sync(FULL, cnt, dd);
        if (lane >= dd) cnt += n;
    }
    unsigned tot = __shfl_sync(FULL, cnt, 31);
    int basepos = 0;
    if (lane == 31 && tot) basepos = atomicAdd(&g_cnt[b], (int)tot);
    basepos = __shfl_sync(FULL, basepos, 31);
    int pos = basepos + (int)(cnt - (unsigned)c);
    for (int q = 0; q < c; q++, pos++)
        if (pos < CAP) g_keys[(size_t)b * CAP + pos] = keys[q];
}

// ---------------- stage A: bitonic sort each 2048-chunk ascending (local direction) ----------------
__global__ void sort2048_kernel() {
    __shared__ unsigned long long sm[2048];
    int b = blockIdx.y, chunk = blockIdx.x, tid = threadIdx.x, T = blockDim.x;
    int gbase = chunk * 2048;
    int cnt = g_cnt[b]; if (cnt > CAP) cnt = CAP;
    for (int i = tid; i < 2048; i += T)
        sm[i] = (gbase + i < cnt) ? g_keys[(size_t)b * CAP + gbase + i] : ~0ull;
    __syncthreads();
    for (int k = 2; k <= 2048; k <<= 1) {
        for (int j = k >> 1; j > 0; j >>= 1) {
            for (int i = tid; i < 2048; i += T) {
                int ixj = i ^ j;
                if (ixj > i) {
                    unsigned long long a = sm[i], cc = sm[ixj];
                    bool up = ((i & k) == 0);           // LOCAL direction: chunk fully ascending
                    if ((a > cc) == up) { sm[i] = cc; sm[ixj] = a; }
                }
            }
            __syncthreads();
        }
    }
    for (int i = tid; i < 2048; i += T) g_keys[(size_t)b * CAP + gbase + i] = sm[i];
}

// ---------------- merge-path merge of two sorted seg-length lists (smem-staged) ----------------
// dir=0: g_keys -> g_keys2.  dir=1: g_keys2 -> g_keys (+ decode top NMS_K when final).
__global__ void merge_kernel(int seg, int dir, int final,
                             const float* __restrict__ loc, const float* __restrict__ prior,
                             int P) {
    extern __shared__ unsigned long long sm[];   // [2*seg]
    int b = blockIdx.y, pairid = blockIdx.x, tid = threadIdx.x, T = blockDim.x;
    const unsigned long long* src = dir ? g_keys2 : g_keys;
    unsigned long long*       dst = dir ? g_keys  : g_keys2;
    size_t base = (size_t)b * CAP + (size_t)pairid * 2 * seg;
    int n2 = 2 * seg;
    for (int i = tid; i < n2; i += T) sm[i] = src[base + i];
    __syncthreads();
    const unsigned long long* A  = sm;
    const unsigned long long* Bv = sm + seg;
    int Q = n2 / T;                  // outputs per thread (4 or 8 at T=1024)
    int d = tid * Q;
    // merge-path binary search: ia = #elements taken from A before diagonal d
    int lo = d - seg; if (lo < 0) lo = 0;
    int hi = d < seg ? d : seg;
    while (lo < hi) {
        int mid = (lo + hi) >> 1;
        if (A[mid] < Bv[d - 1 - mid]) lo = mid + 1; else hi = mid;
    }
    int ia = lo, ib = d - lo;
    for (int q = 0; q < Q; q++) {
        bool fromA = (ib >= seg) || (ia < seg && A[ia] < Bv[ib]);
        unsigned long long key = fromA ? A[ia++] : Bv[ib++];
        int outpos = d + q;
        if (!final) {
            dst[base + outpos] = key;
        } else if (outpos < NMS_K) {
            unsigned idx = (unsigned)key;
            int o = b * NMS_K + outpos;
            if (idx < (unsigned)P) {
                float  sc = __uint_as_float(~(unsigned)(key >> 32));
                float4 l  = reinterpret_cast<const float4*>(loc)[(size_t)b * P + idx];
                float4 pr = reinterpret_cast<const float4*>(prior)[idx];
                float cx = pr.x + l.x * 0.1f * pr.z;
                float cy = pr.y + l.y * 0.1f * pr.w;
                float w  = pr.z * expf(l.z * 0.2f);
                float h  = pr.w * expf(l.w * 0.2f);
                float x1 = cx - w * 0.5f;
                float y1 = cy - h * 0.5f;
                float x2 = x1 + w;
                float y2 = y1 + h;
                g_cscore[o] = sc;
                g_cbox[o]   = make_float4(x1, y1, x2, y2);
                g_carea[o]  = (x2 - x1) * (y2 - y1);
            } else {
                g_cscore[o] = -1.0f;
                g_cbox[o]   = make_float4(0.f, 0.f, 0.f, 0.f);
                g_carea[o]  = 0.0f;
            }
        }
    }
}

// ---------------- suppression bitmatrix (transposed), phased ----------------
__global__ __launch_bounds__(256) void matrix_kernel(int phase, int itile) {
    if (phase && g_need == 0) return;
    __shared__ float4 sbi[ITILE1];
    __shared__ float  sai[ITILE1];
    int b  = blockIdx.y;
    int i0 = blockIdx.x * itile;
    int tid = threadIdx.x, lane = tid & 31, wid = tid >> 5;   // 8 warps

    for (int q = tid; q < itile; q += 256) {
        int i = i0 + q;
        if (i < NMS_K) { sbi[q] = g_cbox[b * NMS_K + i]; sai[q] = g_carea[b * NMS_K + i]; }
        else           { sbi[q] = make_float4(0,0,0,0);  sai[q] = 0.f; }
    }
    __syncthreads();

    int ilim = min(itile, NMS_K - i0);
    int wstart = i0 >> 5;
    int wend   = NWORDS;
    if (phase == 0) wend = PH1_W;
    else if (i0 < PH1_I) wstart = PH1_W;

    for (int w = wstart + wid; w < wend; w += 8) {
        int j = w * 32 + lane;
        bool jv = j < NMS_K;
        float4 bj = jv ? g_cbox[b * NMS_K + j] : make_float4(0,0,0,0);
        float  aj = jv ? g_carea[b * NMS_K + j] : 0.f;
        size_t base = ((size_t)(b * NWORDS + w)) * PAD + i0;
        unsigned myw = 0;
        for (int ii = 0; ii < ilim; ii++) {
            int i = i0 + ii;
            float4 bi = sbi[ii];                      // broadcast (conflict-free)
            float  ai = sai[ii];
            float xx1 = fmaxf(bj.x, bi.x), yy1 = fmaxf(bj.y, bi.y);
            float xx2 = fminf(bj.z, bi.z), yy2 = fminf(bj.w, bi.w);
            float inter = fmaxf(xx2 - xx1, 0.f) * fmaxf(yy2 - yy1, 0.f);
            float uni   = aj - inter + ai;
            // division-free IoU sign test; exact __fdiv_rn only in the boundary band
            float d = fmaf(-NMS_TH, uni, inter);
            bool flag;
            if (fabsf(d) <= 1e-6f * fabsf(uni))
                flag = __fdiv_rn(inter, uni) > NMS_TH;
            else
                flag = d > 0.f;
            flag = flag && jv && (j > i);
            unsigned bal = __ballot_sync(FULL, flag);
            if ((ii & 31) == lane) myw = bal;
            if ((ii & 31) == 31) g_matT[base + (ii - 31) + lane] = myw;   // coalesced
        }
        if (ilim & 31) g_matT[base + (ilim & ~31) + lane] = myw;
    }
}

// ---------------- sweep phase 1: 4-word groups (latency batching); emits if done ----------------
__global__ void sweep1_kernel(float* __restrict__ out) {
    __shared__ unsigned validw[PH1_W];
    __shared__ int      s_acc[TOPK];
    __shared__ int      s_cnt;

    int b = blockIdx.x, tid = threadIdx.x, lane = tid & 31, wid = tid >> 5;

    for (int w = wid; w < PH1_W; w += 8) {
        int i = w * 32 + lane;
        unsigned m = __ballot_sync(FULL, (i < NMS_K) && (g_cscore[b * NMS_K + i] > 0.0f));
        if (lane == 0) validw[w] = m;
    }
    __syncthreads();

    if (wid == 0) {
        int cnt = 0;
        for (int wg = 0; wg < PH1_W && cnt < TOPK; wg += 4) {
            int I0 = wg * 32;
            size_t rowb[4];
            unsigned rem[4], pre[4][4];
            #pragma unroll
            for (int k = 0; k < 4; k++) {
                rowb[k] = ((size_t)(b * NWORDS + wg + k)) * PAD;
                unsigned r = 0;
                for (int q = lane; q < cnt; q += 32) r |= g_matT[rowb[k] + s_acc[q]];
                rem[k] = r;
                #pragma unroll
                for (int a = 0; a <= k; a++)
                    pre[k][a] = g_matT[rowb[k] + I0 + a * 32 + lane];
            }
            #pragma unroll
            for (int k = 0; k < 4; k++) rem[k] = __reduce_or_sync(FULL, rem[k]);
            #pragma unroll
            for (int a = 0; a < 4; a++) {
                if (cnt >= TOPK) break;
                unsigned avail = validw[wg + a] & ~rem[a];
                while (avail && cnt < TOPK) {
                    int bit = __ffs(avail) - 1;
                    if (lane == 0) s_acc[cnt] = I0 + a * 32 + bit;
                    cnt++;
                    avail &= ~(1u << bit);
                    avail &= ~__shfl_sync(FULL, pre[a][a], bit);
                    #pragma unroll
                    for (int k2 = 0; k2 < 4; k2++)
                        if (k2 > a) rem[k2] |= __shfl_sync(FULL, pre[k2][a], bit);
                }
            }
            __syncwarp();
        }
        if (lane == 0) {
            s_cnt = cnt;
            g_scnt[b] = cnt;
            int done = (cnt >= TOPK);
            g_sdone[b] = done;
            if (!done) atomicOr(&g_need, 1);
        }
    }
    __syncthreads();

    int cnt = s_cnt;
    if (cnt >= TOPK) {
        float* orow = out + ((size_t)b * 2 + 1) * TOPK * 5;
        for (int t = tid; t < cnt; t += blockDim.x) {
            int i = s_acc[t];
            float4 bb = g_cbox[b * NMS_K + i];
            float  sc = g_cscore[b * NMS_K + i];
            float* r = orow + t * 5;
            r[0] = sc; r[1] = bb.x; r[2] = bb.y; r[3] = bb.z; r[4] = bb.w;
        }
    } else {
        for (int t = tid; t < cnt; t += blockDim.x) g_acc[b * TOPK + t] = s_acc[t];
    }
}

// ---------------- sweep phase 2: resume + emit (only for unfinished batches) ----------------
__global__ void sweep2_kernel(float* __restrict__ out) {
    __shared__ unsigned validw[NWORDS];
    __shared__ int      s_acc[TOPK];
    __shared__ int      s_cnt;

    int b = blockIdx.x, tid = threadIdx.x, lane = tid & 31, wid = tid >> 5;
    if (g_sdone[b]) return;                       // emitted in sweep1
    int cnt0 = g_scnt[b];

    for (int t = tid; t < cnt0; t += blockDim.x) s_acc[t] = g_acc[b * TOPK + t];
    if (tid == 0) s_cnt = cnt0;

    for (int w = PH1_W + wid; w < NWORDS; w += 8) {
        int i = w * 32 + lane;
        unsigned m = __ballot_sync(FULL, (i < NMS_K) && (g_cscore[b * NMS_K + i] > 0.0f));
        if (lane == 0) validw[w] = m;
    }
    __syncthreads();

    if (wid == 0) {
        int cnt = cnt0;
        for (int w = PH1_W; w < NWORDS && cnt < TOPK; w++) {
            size_t base = ((size_t)(b * NWORDS + w)) * PAD;
            unsigned rem = 0;
            for (int q = lane; q < cnt; q += 32)
                rem |= g_matT[base + s_acc[q]];
            rem = __reduce_or_sync(FULL, rem);
            unsigned pre = g_matT[base + w * 32 + lane];
            unsigned avail = validw[w] & ~rem;
            while (avail && cnt < TOPK) {
                int bit = __ffs(avail) - 1;
                int i = w * 32 + bit;
                if (lane == 0) s_acc[cnt] = i;
                cnt++;
                avail &= ~(1u << bit);
                avail &= ~__shfl_sync(FULL, pre, bit);
            }
            __syncwarp();
        }
        if (lane == 0) s_cnt = cnt;
    }
    __syncthreads();

    int cnt = s_cnt;
    float* orow = out + ((size_t)b * 2 + 1) * TOPK * 5;   // class 1
    for (int t = tid; t < cnt; t += blockDim.x) {
        int i = s_acc[t];
        float4 bb = g_cbox[b * NMS_K + i];
        float  sc = g_cscore[b * NMS_K + i];
        float* r = orow + t * 5;
        r[0] = sc; r[1] = bb.x; r[2] = bb.y; r[3] = bb.z; r[4] = bb.w;
    }
}

// ---------------- launch ----------------
extern "C" void kernel_launch(void* const* d_in, const int* in_sizes, int n_in,
                              void* d_out, int out_size) {
    const float* loc   = (const float*)d_in[0];   // [B,P,4]
    const float* conf  = (const float*)d_in[1];   // [B,P,2]
    const float* prior = (const float*)d_in[2];   // [P,4]

    int P = in_sizes[2] / 4;
    int B = in_sizes[1] / (2 * P);
    if (B > B_MAX) B = B_MAX;
    if (P > P_MAX) P = P_MAX;

    float* out = (float*)d_out;

    cudaFuncSetAttribute(merge_kernel, cudaFuncAttributeMaxDynamicSharedMemorySize, 65536);

    // 1: zero out + histogram + cutoff (last block) + scratch reset
    score_cut_kernel<<<dim3(SGRID, B), 256>>>(conf, out, out_size, P);

    // 2: compact
    dim3 gcomp((P + 1023) / 1024, B);
    compact_kernel<<<gcomp, 256>>>(conf, P);

    // 3: sort four 2048-chunks ascending
    sort2048_kernel<<<dim3(4, B), 1024>>>();

    // 4: merge 2048+2048 -> 4096 (x2), g_keys -> g_keys2   (1024 thr: Q=4)
    merge_kernel<<<dim3(2, B), 1024, 2 * 2048 * 8>>>(2048, 0, 0, loc, prior, P);

    // 5: merge 4096+4096 -> 8192 + decode top NMS_K inline (1024 thr: Q=8)
    merge_kernel<<<dim3(1, B), 1024, 2 * 4096 * 8>>>(4096, 1, 1, loc, prior, P);

    // 6-7: phase-1 matrix (tile 64, short critical path) + grouped sweep
    matrix_kernel<<<dim3(PH1_I / ITILE0, B), 256>>>(0, ITILE0);
    sweep1_kernel<<<B, 256>>>(out);

    // 8-9: phase-2 remainder (early-exits when all batches finished) + resume/emit
    matrix_kernel<<<dim3((NMS_K + ITILE1 - 1) / ITILE1, B), 256>>>(1, ITILE1);
    sweep2_kernel<<<B, 256>>>(out);
}

// round 15
// speedup vs baseline: 1.3588x; 1.1880x over previous
#include <cuda_runtime.h>
#include <cstdint>

#define B_MAX   8
#define P_MAX   140000
#define NBINS   4096
#define CAP     8192       // compact buffer per batch (power of two)
#define NMS_K   5000       // candidates considered by NMS
#define NWORDS  157        // ceil(5000/32)
#define PAD     5120       // padded row length (i-dim) of transposed matrix
#define TOPK    750        // rows emitted per class
#define CONF_TH 0.05f
#define NMS_TH  0.3f
#define FULL    0xffffffffu
#define LOGIT05 -2.9444389791664403f   // logit(0.05)
#define PH1_W   64                      // phase-1 word range [0,64)
#define PH1_I   (PH1_W * 32)            // = 2048 candidates
#define ITILE   128                     // matrix i-tile
#define WTILE   8                       // matrix words per block (1/warp)
#define SGRID   48                      // score grid x-dim

// ---------------- scratch (static device globals; no allocation) ----------------
__device__ unsigned int       g_hist  [B_MAX * NBINS];
__device__ int                g_done  [B_MAX];
__device__ int                g_cnt   [B_MAX];
__device__ int                g_cutbin[B_MAX];
__device__ unsigned long long g_keys  [B_MAX * CAP];
__device__ unsigned long long g_keys2 [B_MAX * CAP];
__device__ float              g_cscore[B_MAX * NMS_K];
__device__ float4             g_cbox  [B_MAX * NMS_K];
__device__ float              g_carea [B_MAX * NMS_K];
__device__ unsigned int       g_matT  [(size_t)B_MAX * NWORDS * PAD];   // ~25.6 MB
// sweep state handoff
__device__ int                g_acc   [B_MAX * TOPK];
__device__ int                g_scnt  [B_MAX];
__device__ int                g_sdone [B_MAX];
__device__ int                g_need;

__device__ __forceinline__ int d_bin(float d) {
    int bin = (int)fmaf(d, 256.0f, 768.0f);        // monotone in d
    return bin > NBINS - 1 ? NBINS - 1 : (bin < 0 ? 0 : bin);
}

// keep predicate: fast d-test with exact softmax fallback in the boundary band
__device__ __forceinline__ bool keep_pred(float c0, float c1, float d) {
    if (fabsf(d - LOGIT05) < 1e-3f) {
        float m  = fmaxf(c0, c1);
        float e0 = expf(c0 - m);
        float e1 = expf(c1 - m);
        return __fdiv_rn(e1, e0 + e1) > CONF_TH;
    }
    return d > LOGIT05;
}

// ---------------- fused: zero out + histogram + (last block) cutoff + scratch reset ----------------
__global__ void score_cut_kernel(const float* __restrict__ conf, float* __restrict__ out,
                                 int out_size, int P) {
    __shared__ unsigned hist[NBINS];
    __shared__ int s_last;
    int b = blockIdx.y;
    int tid = threadIdx.x;

    // zero output (spread over all blocks)
    {
        int t = (blockIdx.y * gridDim.x + blockIdx.x) * blockDim.x + tid;
        int stride = gridDim.x * gridDim.y * blockDim.x;
        for (int i = t; i < out_size; i += stride) out[i] = 0.0f;
    }

    for (int i = tid; i < NBINS; i += blockDim.x) hist[i] = 0u;
    __syncthreads();
    int stride = gridDim.x * blockDim.x;
    const float2* cp = reinterpret_cast<const float2*>(conf) + (size_t)b * P;
    for (int i = blockIdx.x * blockDim.x + tid; i < P; i += stride) {
        float2 c = cp[i];
        float d = c.y - c.x;                         // sigmoid(d) == softmax class-1
        if (keep_pred(c.x, c.y, d))
            atomicAdd(&hist[d_bin(d)], 1u);
    }
    __syncthreads();
    for (int i = tid; i < NBINS; i += blockDim.x)
        if (hist[i]) atomicAdd(&g_hist[b * NBINS + i], hist[i]);

    // last block per batch computes the cutoff and resets scratch
    __threadfence();
    if (tid == 0) {
        int old = atomicAdd(&g_done[b], 1);
        s_last = (old == (int)gridDim.x - 1);
    }
    __syncthreads();
    if (!s_last) return;

    __shared__ unsigned csum[256];
    unsigned sum = 0;
    #pragma unroll
    for (int i = 0; i < NBINS / 256; i++) sum += g_hist[b * NBINS + tid * (NBINS / 256) + i];
    csum[tid] = sum;
    __syncthreads();
    if (tid == 0) {
        unsigned acc = 0;
        int c = 255;
        for (; c >= 0; c--) {
            if (acc + csum[c] >= (unsigned)NMS_K) break;
            acc += csum[c];
        }
        int cut = 0;
        if (c >= 0) {
            int bin = c * (NBINS / 256) + (NBINS / 256) - 1;
            for (; bin >= c * (NBINS / 256); bin--) {
                acc += g_hist[b * NBINS + bin];
                if (acc >= (unsigned)NMS_K) break;
            }
            cut = (bin < c * (NBINS / 256)) ? c * (NBINS / 256) : bin;
        }
        g_cutbin[b] = cut;
        g_cnt[b]  = 0;      // reset for compact (this run)
        g_need    = 0;      // reset for sweep1 (this run)
        g_done[b] = 0;      // reset for next run
    }
    __syncthreads();
    // zero hist for next run (read is complete)
    for (int i = tid; i < NBINS; i += blockDim.x) g_hist[b * NBINS + i] = 0u;
}

// ---------------- compact: recompute d, keep bin>=cut-1, exact s, sortable keys ----------------
__global__ void compact_kernel(const float* __restrict__ conf, int P) {
    int b = blockIdx.y;
    int lane = threadIdx.x & 31;
    int base = (blockIdx.x * blockDim.x + threadIdx.x) * 4;   // 4 anchors/thread
    int cut  = g_cutbin[b] - 1; if (cut < 0) cut = 0;         // one-bin margin (d vs s rounding)
    unsigned long long keys[4];
    int c = 0;
    if (base < P) {
        const float4* cp4 = reinterpret_cast<const float4*>(conf + (size_t)b * P * 2);
        float4 ca = cp4[base / 2];
        float4 cb = cp4[base / 2 + 1];
        float c0s[4] = {ca.x, ca.z, cb.x, cb.z};
        float c1s[4] = {ca.y, ca.w, cb.y, cb.w};
        #pragma unroll
        for (int q = 0; q < 4; q++) {
            if (base + q < P) {
                float c0 = c0s[q], c1 = c1s[q];
                float d = c1 - c0;
                if (keep_pred(c0, c1, d) && d_bin(d) >= cut) {
                    float m  = fmaxf(c0, c1);
                    float e0 = expf(c0 - m);
                    float e1 = expf(c1 - m);
                    float s  = __fdiv_rn(e1, e0 + e1);       // exact ref recipe
                    unsigned kb = __float_as_uint(s);
                    keys[c++] = ((unsigned long long)(~kb) << 32) | (unsigned)(base + q);
                }
            }
        }
    }
    unsigned cnt = (unsigned)c;
    #pragma unroll
    for (int dd = 1; dd < 32; dd <<= 1) {
        unsigned n = __shfl_up_sync(FULL, cnt, dd);
        if (lane >= dd) cnt += n;
    }
    unsigned tot = __shfl_sync(FULL, cnt, 31);
    int basepos = 0;
    if (lane == 31 && tot) basepos = atomicAdd(&g_cnt[b], (int)tot);
    basepos = __shfl_sync(FULL, basepos, 31);
    int pos = basepos + (int)(cnt - (unsigned)c);
    for (int q = 0; q < c; q++, pos++)
        if (pos < CAP) g_keys[(size_t)b * CAP + pos] = keys[q];
}

// ---------------- stage A: bitonic sort each 2048-chunk ascending (local direction) ----------------
__global__ void sort2048_kernel() {
    __shared__ unsigned long long sm[2048];
    int b = blockIdx.y, chunk = blockIdx.x, tid = threadIdx.x, T = blockDim.x;
    int gbase = chunk * 2048;
    int cnt = g_cnt[b]; if (cnt > CAP) cnt = CAP;
    if (gbase >= cnt) {
        // fully past the live keys: store sentinels (stale keys from prior replay!), skip sort
        for (int i = tid; i < 2048; i += T) g_keys[(size_t)b * CAP + gbase + i] = ~0ull;
        return;
    }
    for (int i = tid; i < 2048; i += T)
        sm[i] = (gbase + i < cnt) ? g_keys[(size_t)b * CAP + gbase + i] : ~0ull;
    __syncthreads();
    for (int k = 2; k <= 2048; k <<= 1) {
        for (int j = k >> 1; j > 0; j >>= 1) {
            for (int i = tid; i < 2048; i += T) {
                int ixj = i ^ j;
                if (ixj > i) {
                    unsigned long long a = sm[i], cc = sm[ixj];
                    bool up = ((i & k) == 0);           // LOCAL direction: chunk fully ascending
                    if ((a > cc) == up) { sm[i] = cc; sm[ixj] = a; }
                }
            }
            __syncthreads();
        }
    }
    for (int i = tid; i < 2048; i += T) g_keys[(size_t)b * CAP + gbase + i] = sm[i];
}

// ---------------- merge-path merge of two sorted seg-length lists (smem-staged) ----------------
// dir=0: g_keys -> g_keys2.  dir=1: g_keys2 -> g_keys (+ decode top NMS_K when final).
__global__ void merge_kernel(int seg, int dir, int final,
                             const float* __restrict__ loc, const float* __restrict__ prior,
                             int P) {
    extern __shared__ unsigned long long sm[];   // [2*seg]
    int b = blockIdx.y, pairid = blockIdx.x, tid = threadIdx.x, T = blockDim.x;
    const unsigned long long* src = dir ? g_keys2 : g_keys;
    unsigned long long*       dst = dir ? g_keys  : g_keys2;
    size_t base = (size_t)b * CAP + (size_t)pairid * 2 * seg;
    int n2 = 2 * seg;
    for (int i = tid; i < n2; i += T) sm[i] = src[base + i];
    __syncthreads();
    const unsigned long long* A  = sm;
    const unsigned long long* Bv = sm + seg;
    int Q = n2 / T;                  // outputs per thread (4 or 8 at T=1024)
    int d = tid * Q;
    // merge-path binary search: ia = #elements taken from A before diagonal d
    int lo = d - seg; if (lo < 0) lo = 0;
    int hi = d < seg ? d : seg;
    while (lo < hi) {
        int mid = (lo + hi) >> 1;
        if (A[mid] < Bv[d - 1 - mid]) lo = mid + 1; else hi = mid;
    }
    int ia = lo, ib = d - lo;
    for (int q = 0; q < Q; q++) {
        bool fromA = (ib >= seg) || (ia < seg && A[ia] < Bv[ib]);
        unsigned long long key = fromA ? A[ia++] : Bv[ib++];
        int outpos = d + q;
        if (!final) {
            dst[base + outpos] = key;
        } else if (outpos < NMS_K) {
            unsigned idx = (unsigned)key;
            int o = b * NMS_K + outpos;
            if (idx < (unsigned)P) {
                float  sc = __uint_as_float(~(unsigned)(key >> 32));
                float4 l  = reinterpret_cast<const float4*>(loc)[(size_t)b * P + idx];
                float4 pr = reinterpret_cast<const float4*>(prior)[idx];
                float cx = pr.x + l.x * 0.1f * pr.z;
                float cy = pr.y + l.y * 0.1f * pr.w;
                float w  = pr.z * expf(l.z * 0.2f);
                float h  = pr.w * expf(l.w * 0.2f);
                float x1 = cx - w * 0.5f;
                float y1 = cy - h * 0.5f;
                float x2 = x1 + w;
                float y2 = y1 + h;
                g_cscore[o] = sc;
                g_cbox[o]   = make_float4(x1, y1, x2, y2);
                g_carea[o]  = (x2 - x1) * (y2 - y1);
            } else {
                g_cscore[o] = -1.0f;
                g_cbox[o]   = make_float4(0.f, 0.f, 0.f, 0.f);
                g_carea[o]  = 0.0f;
            }
        }
    }
}

// ---------------- suppression bitmatrix (transposed), 2D-tiled: (i-tile) x (8-word tile) ----------------
// phase 0: i0 < PH1_I, words [0, PH1_W).  phase 1: all i, words [PH1_W, NWORDS).
__global__ __launch_bounds__(256) void matrix_kernel(int phase) {
    if (phase && g_need == 0) return;
    int b  = blockIdx.z;
    int i0 = blockIdx.x * ITILE;
    int w_lo = (phase ? PH1_W : 0) + blockIdx.y * WTILE;
    int w_hi = w_lo + WTILE;
    if (w_hi > NWORDS) w_hi = NWORDS;
    if (w_hi * 32 <= i0) return;                   // entire tile has j <= i: nothing to write

    __shared__ float4 sbi[ITILE];
    __shared__ float  sai[ITILE];
    int tid = threadIdx.x, lane = tid & 31, wid = tid >> 5;   // 8 warps, 1 word each

    for (int q = tid; q < ITILE; q += 256) {
        int i = i0 + q;
        if (i < NMS_K) { sbi[q] = g_cbox[b * NMS_K + i]; sai[q] = g_carea[b * NMS_K + i]; }
        else           { sbi[q] = make_float4(0,0,0,0);  sai[q] = 0.f; }
    }
    __syncthreads();

    int ilim = min(ITILE, NMS_K - i0);
    int wstart = max(w_lo, i0 >> 5);

    int w = wstart + wid;
    if (w >= w_hi) return;
    {
        int j = w * 32 + lane;
        bool jv = j < NMS_K;
        float4 bj = jv ? g_cbox[b * NMS_K + j] : make_float4(0,0,0,0);
        float  aj = jv ? g_carea[b * NMS_K + j] : 0.f;
        size_t base = ((size_t)(b * NWORDS + w)) * PAD + i0;
        unsigned myw = 0;
        for (int ii = 0; ii < ilim; ii++) {
            int i = i0 + ii;
            float4 bi = sbi[ii];                      // broadcast (conflict-free)
            float  ai = sai[ii];
            float xx1 = fmaxf(bj.x, bi.x), yy1 = fmaxf(bj.y, bi.y);
            float xx2 = fminf(bj.z, bi.z), yy2 = fminf(bj.w, bi.w);
            float inter = fmaxf(xx2 - xx1, 0.f) * fmaxf(yy2 - yy1, 0.f);
            float uni   = aj - inter + ai;
            // division-free IoU sign test; exact __fdiv_rn only in the boundary band
            float d = fmaf(-NMS_TH, uni, inter);
            bool flag;
            if (fabsf(d) <= 1e-6f * fabsf(uni))
                flag = __fdiv_rn(inter, uni) > NMS_TH;
            else
                flag = d > 0.f;
            flag = flag && jv && (j > i);
            unsigned bal = __ballot_sync(FULL, flag);
            if ((ii & 31) == lane) myw = bal;
            if ((ii & 31) == 31) g_matT[base + (ii - 31) + lane] = myw;   // coalesced
        }
        if (ilim & 31) g_matT[base + (ilim & ~31) + lane] = myw;
    }
}

// ---------------- sweep phase 1: 8-word groups (latency batching); emits if done ----------------
__global__ void sweep1_kernel(float* __restrict__ out) {
    __shared__ unsigned validw[PH1_W];
    __shared__ int      s_acc[TOPK];
    __shared__ int      s_cnt;

    int b = blockIdx.x, tid = threadIdx.x, lane = tid & 31, wid = tid >> 5;

    for (int w = wid; w < PH1_W; w += 8) {
        int i = w * 32 + lane;
        unsigned m = __ballot_sync(FULL, (i < NMS_K) && (g_cscore[b * NMS_K + i] > 0.0f));
        if (lane == 0) validw[w] = m;
    }
    __syncthreads();

    if (wid == 0) {
        int cnt = 0;
        for (int wg = 0; wg < PH1_W && cnt < TOPK; wg += 8) {
            int I0 = wg * 32;
            size_t rowb[8];
            unsigned rem[8], pre[8][8];
            // all loads for the group issue in parallel (one L2 latency per group)
            #pragma unroll
            for (int k = 0; k < 8; k++) {
                rowb[k] = ((size_t)(b * NWORDS + wg + k)) * PAD;
                unsigned r = 0;
                for (int q = lane; q < cnt; q += 32) r |= g_matT[rowb[k] + s_acc[q]];
                rem[k] = r;
                #pragma unroll
                for (int a = 0; a < 8; a++)
                    pre[k][a] = (a <= k) ? g_matT[rowb[k] + I0 + a * 32 + lane] : 0u;
            }
            #pragma unroll
            for (int k = 0; k < 8; k++) rem[k] = __reduce_or_sync(FULL, rem[k]);
            // sequential pops within group; accepts propagate into later words via shfl
            #pragma unroll
            for (int a = 0; a < 8; a++) {
                if (cnt >= TOPK) break;
                unsigned avail = validw[wg + a] & ~rem[a];
                while (avail && cnt < TOPK) {
                    int bit = __ffs(avail) - 1;
                    if (lane == 0) s_acc[cnt] = I0 + a * 32 + bit;
                    cnt++;
                    avail &= ~(1u << bit);
                    avail &= ~__shfl_sync(FULL, pre[a][a], bit);
                    #pragma unroll
                    for (int k2 = 0; k2 < 8; k2++)
                        if (k2 > a) rem[k2] |= __shfl_sync(FULL, pre[k2][a], bit);
                }
            }
            __syncwarp();
        }
        if (lane == 0) {
            s_cnt = cnt;
            g_scnt[b] = cnt;
            int done = (cnt >= TOPK);
            g_sdone[b] = done;
            if (!done) atomicOr(&g_need, 1);
        }
    }
    __syncthreads();

    int cnt = s_cnt;
    if (cnt >= TOPK) {
        float* orow = out + ((size_t)b * 2 + 1) * TOPK * 5;
        for (int t = tid; t < cnt; t += blockDim.x) {
            int i = s_acc[t];
            float4 bb = g_cbox[b * NMS_K + i];
            float  sc = g_cscore[b * NMS_K + i];
            float* r = orow + t * 5;
            r[0] = sc; r[1] = bb.x; r[2] = bb.y; r[3] = bb.z; r[4] = bb.w;
        }
    } else {
        for (int t = tid; t < cnt; t += blockDim.x) g_acc[b * TOPK + t] = s_acc[t];
    }
}

// ---------------- sweep phase 2: 8-word groups; resume + emit (only for unfinished batches) ----------------
__global__ void sweep2_kernel(float* __restrict__ out) {
    __shared__ unsigned validw[NWORDS];
    __shared__ int      s_acc[TOPK];
    __shared__ int      s_cnt;

    int b = blockIdx.x, tid = threadIdx.x, lane = tid & 31, wid = tid >> 5;
    if (g_sdone[b]) return;                       // emitted in sweep1
    int cnt0 = g_scnt[b];

    for (int t = tid; t < cnt0; t += blockDim.x) s_acc[t] = g_acc[b * TOPK + t];
    if (tid == 0) s_cnt = cnt0;

    for (int w = PH1_W + wid; w < NWORDS; w += 8) {
        int i = w * 32 + lane;
        unsigned m = __ballot_sync(FULL, (i < NMS_K) && (g_cscore[b * NMS_K + i] > 0.0f));
        if (lane == 0) validw[w] = m;
    }
    __syncthreads();

    if (wid == 0) {
        int cnt = cnt0;
        for (int wg = PH1_W; wg < NWORDS && cnt < TOPK; wg += 8) {
            int kl = NWORDS - wg; if (kl > 8) kl = 8;
            int I0 = wg * 32;
            size_t rowb[8];
            unsigned rem[8], pre[8][8];
            #pragma unroll
            for (int k = 0; k < 8; k++) {
                if (k < kl) {
                    rowb[k] = ((size_t)(b * NWORDS + wg + k)) * PAD;
                    unsigned r = 0;
                    for (int q = lane; q < cnt; q += 32) r |= g_matT[rowb[k] + s_acc[q]];
                    rem[k] = r;
                    #pragma unroll
                    for (int a = 0; a < 8; a++)
                        pre[k][a] = (a <= k) ? g_matT[rowb[k] + I0 + a * 32 + lane] : 0u;
                } else {
                    rem[k] = 0u;
                    #pragma unroll
                    for (int a = 0; a < 8; a++) pre[k][a] = 0u;
                }
            }
            #pragma unroll
            for (int k = 0; k < 8; k++) rem[k] = __reduce_or_sync(FULL, rem[k]);
            #pragma unroll
            for (int a = 0; a < 8; a++) {
                if (a >= kl || cnt >= TOPK) break;
                unsigned avail = validw[wg + a] & ~rem[a];
                while (avail && cnt < TOPK) {
                    int bit = __ffs(avail) - 1;
                    if (lane == 0) s_acc[cnt] = I0 + a * 32 + bit;
                    cnt++;
                    avail &= ~(1u << bit);
                    avail &= ~__shfl_sync(FULL, pre[a][a], bit);
                    #pragma unroll
                    for (int k2 = 0; k2 < 8; k2++)
                        if (k2 > a) rem[k2] |= __shfl_sync(FULL, pre[k2][a], bit);
                }
            }
            __syncwarp();
        }
        if (lane == 0) s_cnt = cnt;
    }
    __syncthreads();

    int cnt = s_cnt;
    float* orow = out + ((size_t)b * 2 + 1) * TOPK * 5;   // class 1
    for (int t = tid; t < cnt; t += blockDim.x) {
        int i = s_acc[t];
        float4 bb = g_cbox[b * NMS_K + i];
        float  sc = g_cscore[b * NMS_K + i];
        float* r = orow + t * 5;
        r[0] = sc; r[1] = bb.x; r[2] = bb.y; r[3] = bb.z; r[4] = bb.w;
    }
}

// ---------------- launch ----------------
extern "C" void kernel_launch(void* const* d_in, const int* in_sizes, int n_in,
                              void* d_out, int out_size) {
    const float* loc   = (const float*)d_in[0];   // [B,P,4]
    const float* conf  = (const float*)d_in[1];   // [B,P,2]
    const float* prior = (const float*)d_in[2];   // [P,4]

    int P = in_sizes[2] / 4;
    int B = in_sizes[1] / (2 * P);
    if (B > B_MAX) B = B_MAX;
    if (P > P_MAX) P = P_MAX;

    float* out = (float*)d_out;

    cudaFuncSetAttribute(merge_kernel, cudaFuncAttributeMaxDynamicSharedMemorySize, 65536);

    // 1: zero out + histogram + cutoff (last block) + scratch reset
    score_cut_kernel<<<dim3(SGRID, B), 256>>>(conf, out, out_size, P);

    // 2: compact
    dim3 gcomp((P + 1023) / 1024, B);
    compact_kernel<<<gcomp, 256>>>(conf, P);

    // 3: sort four 2048-chunks ascending (all-sentinel chunks skip the sort)
    sort2048_kernel<<<dim3(4, B), 1024>>>();

    // 4: merge 2048+2048 -> 4096 (x2), g_keys -> g_keys2   (1024 thr: Q=4)
    merge_kernel<<<dim3(2, B), 1024, 2 * 2048 * 8>>>(2048, 0, 0, loc, prior, P);

    // 5: merge 4096+4096 -> 8192 + decode top NMS_K inline (1024 thr: Q=8)
    merge_kernel<<<dim3(1, B), 1024, 2 * 4096 * 8>>>(4096, 1, 1, loc, prior, P);

    // 6-7: phase-1 matrix (2D-tiled: 16 i-tiles x 8 word-tiles) + grouped sweep
    matrix_kernel<<<dim3(PH1_I / ITILE, PH1_W / WTILE, B), 256>>>(0);
    sweep1_kernel<<<B, 256>>>(out);

    // 8-9: phase-2 remainder (2D-tiled; early-exits when all batches finished) + resume/emit
    {
        int wtiles = (NWORDS - PH1_W + WTILE - 1) / WTILE;
        matrix_kernel<<<dim3((NMS_K + ITILE - 1) / ITILE, wtiles, B), 256>>>(1);
    }
    sweep2_kernel<<<B, 256>>>(out);
}